// round 12
// baseline (speedup 1.0000x reference)
#include <cuda_runtime.h>
#include <math.h>

// ---------------------------------------------------------------------------
// Constants fixed by setup_inputs
// ---------------------------------------------------------------------------
#define NF      32
#define XS      576        // 2*9*32 floats per node
#define NNODE   1024
#define NMOL    32
#define NATOM   32
#define EPM     992
#define NEDGE   31744

// ---------------------------------------------------------------------------
// Compile-time Clebsch-Gordan per-entry evaluation (replicates _build_cg).
// ---------------------------------------------------------------------------
namespace cg {

__host__ __device__ constexpr double fact(int n) {
    double r = 1.0; for (int i = 2; i <= n; i++) r *= (double)i; return r;
}

__host__ __device__ constexpr double csqrt(double x) {
    if (x <= 0.0) return 0.0;
    double g = (x > 1.0) ? x : 1.0;
    for (int i = 0; i < 100; i++) g = 0.5 * (g + x / g);
    return g;
}

__host__ __device__ constexpr double cgc(int j1, int m1, int j2, int m2, int J, int M) {
    if (m1 + m2 != M) return 0.0;
    int ad = j1 - j2; if (ad < 0) ad = -ad;
    if (J < ad || J > j1 + j2) return 0.0;
    double pref = (2.0 * J + 1.0) * fact(J + j1 - j2) * fact(J - j1 + j2) * fact(j1 + j2 - J)
                  / fact(j1 + j2 + J + 1);
    pref *= fact(J + M) * fact(J - M) * fact(j1 - m1) * fact(j1 + m1) * fact(j2 - m2) * fact(j2 + m2);
    double s = 0.0;
    for (int k = 0; k <= j1 + j2; k++) {
        int d0 = j1 + j2 - J - k, d1 = j1 - m1 - k, d2 = j2 + m2 - k;
        int d3 = J - j2 + m1 + k, d4 = J - j1 - m2 + k;
        if (d0 < 0 || d1 < 0 || d2 < 0 || d3 < 0 || d4 < 0) continue;
        double t = 1.0 / (fact(k) * fact(d0) * fact(d1) * fact(d2) * fact(d3) * fact(d4));
        s += (k & 1) ? -t : t;
    }
    return csqrt(pref) * s;
}

struct C2 { double re, im; };
struct URow { int n; int col[2]; C2 v[2]; };

__host__ __device__ constexpr URow urow(int l, int rr) {
    URow u{};
    const double R2 = 0.70710678118654752440;
    if (rr == l) { u.n = 1; u.col[0] = l; u.v[0].re = 1.0; u.v[0].im = 0.0; return u; }
    if (rr > l) {
        int m = rr - l; double sg = (m & 1) ? -1.0 : 1.0;
        u.n = 2;
        u.col[0] = l + m; u.v[0].re = sg * R2; u.v[0].im = 0.0;
        u.col[1] = l - m; u.v[1].re = R2;      u.v[1].im = 0.0;
        return u;
    }
    int m = l - rr; double sg = (m & 1) ? -1.0 : 1.0;
    u.n = 2;
    u.col[0] = l - m; u.v[0].re = 0.0; u.v[0].im = R2;
    u.col[1] = l + m; u.v[1].re = 0.0; u.v[1].im = -sg * R2;
    return u;
}

__host__ __device__ constexpr int dm(int i) { return (i == 0) ? 0 : ((i < 4) ? 1 : 2); }

__host__ __device__ constexpr float cg_entry(int A, int B, int C) {
    int l1 = dm(A), l2 = dm(B), l3 = dm(C);
    int a = A - l1 * l1, b = B - l2 * l2, c = C - l3 * l3;
    double gre = 0.0, gim = 0.0;
    int ad = l1 - l2; if (ad < 0) ad = -ad;
    if (l3 >= ad && l3 <= l1 + l2) {
        URow u1 = urow(l1, a), u2 = urow(l2, b), u3 = urow(l3, c);
        for (int i = 0; i < u1.n; i++)
            for (int j = 0; j < u2.n; j++)
                for (int k = 0; k < u3.n; k++) {
                    double cv = cgc(l1, u1.col[i] - l1, l2, u2.col[j] - l2,
                                    l3, u3.col[k] - l3);
                    if (cv == 0.0) continue;
                    double pre = u1.v[i].re * u2.v[j].re - u1.v[i].im * u2.v[j].im;
                    double pim = u1.v[i].re * u2.v[j].im + u1.v[i].im * u2.v[j].re;
                    double re = pre * u3.v[k].re + pim * u3.v[k].im;   // * conj(v3)
                    double im = pim * u3.v[k].re - pre * u3.v[k].im;
                    gre += re * cv; gim += im * cv;
                }
    }
    double agre = (gre < 0) ? -gre : gre;
    double agim = (gim < 0) ? -gim : gim;
    double R = (agim > agre) ? gim : gre;
    return (float)R;
}

__host__ __device__ constexpr bool in_half(int i, int h) { return h == 0 ? (i < 5) : (i >= 5); }

// Is A[a][b] needed for ANY kept output c under maxdeg MD?
__host__ __device__ constexpr bool ab_used(int a, int b, int md) {
    for (int c = 0; c < 9; c++) {
        bool keep = (md == 2) || (c == 0);
        if (keep && cg_entry(a, b, c) != 0.0f) return true;
    }
    return false;
}
__host__ __device__ constexpr bool ab_used_h(int a, int b, int md, int h) {
    return in_half(b, h) && ab_used(a, b, md);
}
__host__ __device__ constexpr bool need_same_h(int a, int md, int h) {
    for (int b = 0; b < 9; b++)
        if (!(b >= 1 && b <= 3) && ab_used_h(a, b, md, h)) return true;
    return false;
}
__host__ __device__ constexpr bool need_flip_h(int a, int md, int h) {
    for (int b = 1; b <= 3; b++)
        if (ab_used_h(a, b, md, h)) return true;
    return false;
}
__host__ __device__ constexpr bool need_lb(int l, int md, int h) {
    for (int a = 0; a < 9; a++)
        for (int b = 0; b < 9; b++)
            if (dm(b) == l && ab_used_h(a, b, md, h)) return true;
    return false;
}

} // namespace cg

// ---------------------------------------------------------------------------
// Device scratch (static, no allocation)
// ---------------------------------------------------------------------------
__device__ float g_r[NEDGE];
__device__ float g_sh[NEDGE * 12];   // padded to 12 for float4 loads
__device__ float g_rad[NEDGE * 8];

__device__ float g_xbuf[2][NNODE * XS];   // ping-pong node state
__device__ float g_xEF[NNODE * XS];
__device__ float g_q[NNODE];
__device__ float g_aE[NNODE];
__device__ float g_dip[NNODE * 3];

__device__ __forceinline__ float warp_sum(float v) {
#pragma unroll
    for (int o = 16; o; o >>= 1) v += __shfl_xor_sync(0xffffffffu, v, o);
    return v;
}
__device__ __forceinline__ float sigm(float x) { return 1.0f / (1.0f + expf(-x)); }

// ---------------------------------------------------------------------------
// Compile-time helpers (ALL CG queries inside if constexpr — R10 lesson)
// ---------------------------------------------------------------------------
// partial CG contraction (only A entries with b in half H)
template<int AB, int C, int MD, int H>
__device__ __forceinline__ void cg_contract_c(const float (&A)[81], float (&y)[9]) {
    if constexpr (C < 9) {
        constexpr float v = cg::cg_entry(AB / 9, AB % 9, C);
        constexpr bool keep = (MD == 2) || (C == 0);
        if constexpr (v != 0.0f && keep && cg::in_half(AB % 9, H)) { y[C] += v * A[AB]; }
        cg_contract_c<AB, C + 1, MD, H>(A, y);
    }
}
template<int AB, int MD, int H>
__device__ __forceinline__ void cg_contract_ab(const float (&A)[81], float (&y)[9]) {
    if constexpr (AB < 81) {
        cg_contract_c<AB, 0, MD, H>(A, y);
        cg_contract_ab<AB + 1, MD, H>(A, y);
    }
}

// per-edge A accumulation, b restricted to half H
template<int AB, int MD, int H>
__device__ __forceinline__ void accum_ab(float (&A)[81], const float (&xsame)[9],
                                         const float (&xflip)[9], const float (&g)[9]) {
    if constexpr (AB < 81) {
        constexpr int a = AB / 9;
        constexpr int b = AB % 9;
        if constexpr (cg::ab_used_h(a, b, MD, H)) {
            float xa = (b >= 1 && b <= 3) ? xflip[a] : xsame[a];
            A[AB] += xa * g[b];
        }
        accum_ab<AB + 1, MD, H>(A, xsame, xflip, g);
    }
}

// guarded x loads
template<int AA, int MD, int H>
__device__ __forceinline__ void load_x(float (&xsame)[9], float (&xflip)[9],
                                       const float* __restrict__ xs,
                                       int sameoff, int flipoff, int lane) {
    if constexpr (AA < 9) {
        if constexpr (cg::need_same_h(AA, MD, H)) xsame[AA] = xs[sameoff + AA * NF + lane];
        else                                      xsame[AA] = 0.0f;
        if constexpr (cg::need_flip_h(AA, MD, H)) xflip[AA] = xs[flipoff + AA * NF + lane];
        else                                      xflip[AA] = 0.0f;
        load_x<AA + 1, MD, H>(xsame, xflip, xs, sameoff, flipoff, lane);
    }
}

// couple producing only outputs c in half H (for output parity chosen by VP/VQ)
template<int AB, int C, int MAXC, int H>
__device__ __forceinline__ void couple1_c(const float (&U0)[9], const float (&U1)[9],
                                          const float (&VP)[9], const float (&VQ)[9],
                                          const float (&wt)[27], float (&O)[9]) {
    if constexpr (C < MAXC) {
        constexpr int a = AB / 9;
        constexpr int b = AB % 9;
        constexpr float v = cg::cg_entry(a, b, C);
        if constexpr (v != 0.0f && cg::in_half(C, H)) {
            constexpr int lidx = cg::dm(a) * 9 + cg::dm(b) * 3 + cg::dm(C);
            float wv = v * wt[lidx];
            O[C] += wv * (U0[a] * VP[b] + U1[a] * VQ[b]);
        }
        couple1_c<AB, C + 1, MAXC, H>(U0, U1, VP, VQ, wt, O);
    }
}
template<int AB, int MAXC, int H>
__device__ __forceinline__ void couple1_ab(const float (&U0)[9], const float (&U1)[9],
                                           const float (&VP)[9], const float (&VQ)[9],
                                           const float (&wt)[27], float (&O)[9]) {
    if constexpr (AB < 81) {
        couple1_c<AB, 0, MAXC, H>(U0, U1, VP, VQ, wt, O);
        couple1_ab<AB + 1, MAXC, H>(U0, U1, VP, VQ, wt, O);
    }
}
template<int MAXC, int H>
__device__ __forceinline__ void couple1(const float (&U0)[9], const float (&U1)[9],
                                        const float (&VP)[9], const float (&VQ)[9],
                                        const float (&wt)[27], float (&O)[9]) {
#pragma unroll
    for (int c = 0; c < 9; c++) O[c] = 0.0f;
    couple1_ab<0, MAXC, H>(U0, U1, VP, VQ, wt, O);
}

// ---------------------------------------------------------------------------
// Per-warp dense of NR rows (row-local) via smem staging + float4 LDS.
// ---------------------------------------------------------------------------
template<int NR>
__device__ __forceinline__ void dense_rows(float (&X)[NR], const float* __restrict__ W,
                                           int lane, float* scr) {
    float wc[32];
#pragma unroll
    for (int k = 0; k < 32; k++) wc[k] = W[k * NF + lane];
    __syncwarp();
#pragma unroll
    for (int r = 0; r < NR; r++) scr[r * NF + lane] = X[r];
    __syncwarp();
#pragma unroll
    for (int r = 0; r < NR; r++) {
        const float4* rp = (const float4*)(scr + r * NF);
        float a = 0.0f;
#pragma unroll
        for (int kk = 0; kk < 8; kk++) {
            float4 v = rp[kk];
            a += v.x * wc[kk * 4 + 0] + v.y * wc[kk * 4 + 1]
               + v.z * wc[kk * 4 + 2] + v.w * wc[kk * 4 + 3];
        }
        X[r] = a;
    }
    __syncwarp();
}

// ---------------------------------------------------------------------------
// Fused edge precompute + state init (128 blocks x 256)
// ---------------------------------------------------------------------------
__global__ void __launch_bounds__(256) edgeinit_kernel(
    const float* __restrict__ pos,
    const int* __restrict__ dst_idx, const int* __restrict__ src_idx,
    const int* __restrict__ Zarr, const float* __restrict__ embed,
    const float* __restrict__ Ef) {
    int e = blockIdx.x * 256 + threadIdx.x;
    if (e < NEDGE) {
        int mol = e / EPM, k = e % EPM;
        int d = dst_idx[k] + mol * NATOM;
        int s = src_idx[k] + mol * NATOM;
        float dx = pos[s * 3 + 0] - pos[d * 3 + 0];
        float dy = pos[s * 3 + 1] - pos[d * 3 + 1];
        float dz = pos[s * 3 + 2] - pos[d * 3 + 2];
        float r = sqrtf(dx * dx + dy * dy + dz * dz);
        g_r[e] = r;
        float inv = 1.0f / (r + 1e-10f);
        float x = dx * inv, y = dy * inv, z = dz * inv;
        const float s3 = 1.7320508075688772f;
        g_sh[e * 12 + 0] = 1.0f;
        g_sh[e * 12 + 1] = y;
        g_sh[e * 12 + 2] = z;
        g_sh[e * 12 + 3] = x;
        g_sh[e * 12 + 4] = s3 * x * y;
        g_sh[e * 12 + 5] = s3 * y * z;
        g_sh[e * 12 + 6] = 0.5f * (3.0f * z * z - 1.0f);
        g_sh[e * 12 + 7] = s3 * x * z;
        g_sh[e * 12 + 8] = 0.5f * s3 * (x * x - y * y);

        float fb = 1.0f / (1.0f + r);
        float omf = 1.0f - fb;
        float u2 = (r * 0.2f) * (r * 0.2f);
        float inner = fmaxf(1.0f - u2, 1e-6f);
        float cut = (r < 5.0f) ? expf(1.0f - 1.0f / inner) : 0.0f;
        const float binom[8] = {1.f, 7.f, 21.f, 35.f, 35.f, 21.f, 7.f, 1.f};
        float fp[8], op[8];
        fp[0] = 1.0f; op[0] = 1.0f;
#pragma unroll
        for (int i = 1; i < 8; i++) { fp[i] = fp[i - 1] * fb; op[i] = op[i - 1] * omf; }
#pragma unroll
        for (int i = 0; i < 8; i++)
            g_rad[e * 8 + i] = binom[i] * fp[i] * op[7 - i] * cut;
    }

    int node = blockIdx.x * 8 + (threadIdx.x >> 5);
    int lane = threadIdx.x & 31;
    int mol = node >> 5;
    int Z = Zarr[node];
    float* xo = g_xbuf[0] + node * XS;
    float* xe = g_xEF + node * XS;
    float e0 = Ef[mol * 3 + 0], e1 = Ef[mol * 3 + 1], e2 = Ef[mol * 3 + 2];
#pragma unroll
    for (int p = 0; p < 2; p++)
#pragma unroll
        for (int m = 0; m < 9; m++) {
            float xv = (p == 0 && m == 0) ? embed[Z * NF + lane] : 0.0f;
            float ev = (m == 1) ? e0 : ((m == 2) ? e1 : ((m == 3) ? e2 : 0.0f));
            xo[(p * 9 + m) * NF + lane] = xv;
            xe[(p * 9 + m) * NF + lane] = ev;
        }
}

// ---------------------------------------------------------------------------
// Kernel parameter bundle
// ---------------------------------------------------------------------------
struct KParams {
    const float* Wmp; const float* Wd; const float* bd;
    const float* Wt; const float* Wtd1; const float* Wtd2; const float* Wtdp;
    const float* Wh; const float* bh; const float* Wq;
    const float* Wdip1; const float* Wdip2; const float* Wdipp; const float* wdip;
    const float* We; const float* be; const float* ebias;
    const int* Zarr;
};

// ---------------------------------------------------------------------------
// Per-warp work: msg (b-half H of parity p) + update (m-rows in half H).
// Warp layout: wid = p*2 + h.
// ---------------------------------------------------------------------------
template<int MD, bool RO, int H>
__device__ __forceinline__ void run_warp(
    int p, int lane, int node, int inbuf, int iter, const KParams& kp,
    float (*sBuf)[9 * NF], float* scr, float* sG) {

    constexpr int NR = (H == 0) ? 5 : 4;
    constexpr int MB = (H == 0) ? 0 : 5;

    int mol = node >> 5, datom = node & 31;
    const float* xin = g_xbuf[inbuf];

    // ================= message =================
    float wmp0[8], wmp1[8], wmp2[8];
#pragma unroll
    for (int nb = 0; nb < 8; nb++) {
        if constexpr (cg::need_lb(0, MD, H)) wmp0[nb] = kp.Wmp[((iter * 3 + 0) * 8 + nb) * NF + lane];
        else wmp0[nb] = 0.0f;
        if constexpr (cg::need_lb(1, MD, H)) wmp1[nb] = kp.Wmp[((iter * 3 + 1) * 8 + nb) * NF + lane];
        else wmp1[nb] = 0.0f;
        if constexpr (cg::need_lb(2, MD, H)) wmp2[nb] = kp.Wmp[((iter * 3 + 2) * 8 + nb) * NF + lane];
        else wmp2[nb] = 0.0f;
    }

    float A[81];
#pragma unroll
    for (int i = 0; i < 81; i++) A[i] = 0.0f;

    int ebase = mol * EPM + datom * 31;
    int sameoff = p * 288;
    int flipoff = 288 - sameoff;
    const float* xmol = xin + mol * NATOM * XS;

    for (int t = 0; t < 31; t++) {
        int e = ebase + t;
        int satom = t + (t >= datom ? 1 : 0);
        const float* xs = xmol + satom * XS;

        float4 ra = *(const float4*)(g_rad + e * 8);
        float4 rb = *(const float4*)(g_rad + e * 8 + 4);
        float R0 = 0.0f, R1 = 0.0f, R2v = 0.0f;
        if constexpr (cg::need_lb(0, MD, H))
            R0 = ra.x * wmp0[0] + ra.y * wmp0[1] + ra.z * wmp0[2] + ra.w * wmp0[3]
               + rb.x * wmp0[4] + rb.y * wmp0[5] + rb.z * wmp0[6] + rb.w * wmp0[7];
        if constexpr (cg::need_lb(1, MD, H))
            R1 = ra.x * wmp1[0] + ra.y * wmp1[1] + ra.z * wmp1[2] + ra.w * wmp1[3]
               + rb.x * wmp1[4] + rb.y * wmp1[5] + rb.z * wmp1[6] + rb.w * wmp1[7];
        if constexpr (cg::need_lb(2, MD, H))
            R2v = ra.x * wmp2[0] + ra.y * wmp2[1] + ra.z * wmp2[2] + ra.w * wmp2[3]
                + rb.x * wmp2[4] + rb.y * wmp2[5] + rb.z * wmp2[6] + rb.w * wmp2[7];

        float4 s0 = *(const float4*)(g_sh + e * 12);
        float4 s1 = *(const float4*)(g_sh + e * 12 + 4);
        float  s8 = g_sh[e * 12 + 8];
        float g[9];
        g[0] = s0.x * R0;
        g[1] = s0.y * R1; g[2] = s0.z * R1; g[3] = s0.w * R1;
        g[4] = s1.x * R2v; g[5] = s1.y * R2v; g[6] = s1.z * R2v;
        g[7] = s1.w * R2v; g[8] = s8 * R2v;

        float xsame[9], xflip[9];
        load_x<0, MD, H>(xsame, xflip, xs, sameoff, flipoff, lane);
        accum_ab<0, MD, H>(A, xsame, xflip, g);
    }

    float Yp[9];
#pragma unroll
    for (int c = 0; c < 9; c++) Yp[c] = 0.0f;
    cg_contract_ab<0, MD, H>(A, Yp);

    // stage partial Y; slot = p*2 + H
#pragma unroll
    for (int m = 0; m < 9; m++) sBuf[p * 2 + H][m * NF + lane] = Yp[m];
    __syncthreads();

    // total Y for my rows
    float Y[NR];
#pragma unroll
    for (int r = 0; r < NR; r++)
        Y[r] = sBuf[p * 2 + 0][(MB + r) * NF + lane] + sBuf[p * 2 + 1][(MB + r) * NF + lane];

    // ================= update =================
    float X[NR];
    const float* xg = xin + node * XS + p * 288;
#pragma unroll
    for (int r = 0; r < NR; r++) X[r] = xg[(MB + r) * NF + lane] + Y[r];

    // gate 1 (sigm of parity0 m0 — owned by warp (0,0))
    if (p == 0 && H == 0) sG[lane] = X[0];
    __syncthreads();   // also guarantees all warps finished reading sBuf partial Ys
    float gate = sigm(sG[lane]);
#pragma unroll
    for (int r = 0; r < NR; r++) X[r] *= gate;

    // dense Wd (own rows) + bias + gate 2
    dense_rows<NR>(X, kp.Wd + iter * NF * NF, lane, scr);
    if (p == 0 && H == 0) X[0] += kp.bd[iter * NF + lane];
    __syncthreads();
    if (p == 0 && H == 0) sG[lane] = X[0];
    __syncthreads();
    gate = sigm(sG[lane]);
#pragma unroll
    for (int r = 0; r < NR; r++) X[r] *= gate;

    // couple(x, xEF, Wt): stage X -> sBuf[p], E -> sBuf[2+p]
    float* xeg = g_xEF + node * XS + p * 288;
    float E[NR];
#pragma unroll
    for (int r = 0; r < NR; r++) {
        E[r] = xeg[(MB + r) * NF + lane];
        sBuf[p][(MB + r) * NF + lane] = X[r];
        sBuf[2 + p][(MB + r) * NF + lane] = E[r];
    }
    __syncthreads();
    float wt[27];
#pragma unroll
    for (int j = 0; j < 27; j++) wt[j] = kp.Wt[(iter * 27 + j) * NF + lane];
    {
        float U0[9], U1[9], VP[9], VQ[9];
#pragma unroll
        for (int m = 0; m < 9; m++) {
            U0[m] = sBuf[0][m * NF + lane];
            U1[m] = sBuf[1][m * NF + lane];
            VP[m] = sBuf[2 + p][m * NF + lane];
            VQ[m] = sBuf[3 - p][m * NF + lane];
        }
        float O[9];
        couple1<9, H>(U0, U1, VP, VQ, wt, O);
#pragma unroll
        for (int r = 0; r < NR; r++) {
            xeg[(MB + r) * NF + lane] = O[MB + r];
            X[r] += O[MB + r];
        }
    }

    // tensor_dense: U = X@Wtd1, V = X@Wtd2 (own rows), couple
    float U[NR], V[NR];
#pragma unroll
    for (int r = 0; r < NR; r++) { U[r] = X[r]; V[r] = X[r]; }
    dense_rows<NR>(U, kp.Wtd1 + iter * NF * NF, lane, scr);
    dense_rows<NR>(V, kp.Wtd2 + iter * NF * NF, lane, scr);
    __syncthreads();   // all couple reads done before restaging
#pragma unroll
    for (int r = 0; r < NR; r++) {
        sBuf[p][(MB + r) * NF + lane] = U[r];
        sBuf[2 + p][(MB + r) * NF + lane] = V[r];
    }
    __syncthreads();
#pragma unroll
    for (int j = 0; j < 27; j++) wt[j] = kp.Wtdp[(iter * 27 + j) * NF + lane];
    {
        float U0[9], U1[9], VP[9], VQ[9];
#pragma unroll
        for (int m = 0; m < 9; m++) {
            U0[m] = sBuf[0][m * NF + lane];
            U1[m] = sBuf[1][m * NF + lane];
            VP[m] = sBuf[2 + p][m * NF + lane];
            VQ[m] = sBuf[3 - p][m * NF + lane];
        }
        float O[9];
        couple1<9, H>(U0, U1, VP, VQ, wt, O);
#pragma unroll
        for (int r = 0; r < NR; r++) X[r] = O[MB + r] + Y[r];
    }

    if constexpr (!RO) {
        float* xo = g_xbuf[inbuf ^ 1] + node * XS + p * 288;
#pragma unroll
        for (int r = 0; r < NR; r++) xo[(MB + r) * NF + lane] = X[r];
        return;
    } else {
        // ================= readout =================
#pragma unroll
        for (int i = 0; i < 4; i++) {
            dense_rows<NR>(X, kp.Wh + i * NF * NF, lane, scr);
            if (p == 0 && H == 0) X[0] += kp.bh[i * NF + lane];
            __syncthreads();
            if (p == 0 && H == 0) sG[lane] = X[0];
            __syncthreads();
            float g2 = sigm(sG[lane]);
#pragma unroll
            for (int r = 0; r < NR; r++) X[r] *= g2;
        }
        dense_rows<NR>(X, kp.Wh + 4 * NF * NF, lane, scr);
        if (p == 0 && H == 0) X[0] += kp.bh[4 * NF + lane];

        // charges + site energy (warp (0,0))
        if (p == 0 && H == 0) {
            float scal = X[0];
            float q = warp_sum(scal * kp.Wq[lane]);
            float ae = warp_sum(scal * kp.We[lane]);
            if (lane == 0) {
                g_q[node] = q;
                g_aE[node] = ae + kp.be[0] + kp.ebias[kp.Zarr[node]];
            }
        }

        // dipole path: xd keeps [p0,m0] and [p1,m1..3] (both in half 0)
        float Ud[NR], Vd[NR];
#pragma unroll
        for (int r = 0; r < NR; r++) Ud[r] = 0.0f;
        if constexpr (H == 0) {
            if (p == 0) { Ud[0] = X[0]; }
            else        { Ud[1] = X[1]; Ud[2] = X[2]; Ud[3] = X[3]; }
        }
#pragma unroll
        for (int r = 0; r < NR; r++) Vd[r] = Ud[r];
        dense_rows<NR>(Ud, kp.Wdip1, lane, scr);
        dense_rows<NR>(Vd, kp.Wdip2, lane, scr);
        __syncthreads();
#pragma unroll
        for (int r = 0; r < NR; r++) {
            sBuf[p][(MB + r) * NF + lane] = Ud[r];
            sBuf[2 + p][(MB + r) * NF + lane] = Vd[r];
        }
        __syncthreads();

        // dipole couple: output parity 1, c in 1..3 (half 0) -> warp (1,0)
        if (H == 0 && p == 1) {
            float wtd[27];
#pragma unroll
            for (int j = 0; j < 27; j++) wtd[j] = kp.Wdipp[j * NF + lane];
            float U0[9], U1[9], VP[9], VQ[9];
#pragma unroll
            for (int m = 0; m < 9; m++) {
                U0[m] = sBuf[0][m * NF + lane];
                U1[m] = sBuf[1][m * NF + lane];
                VP[m] = sBuf[3][m * NF + lane];   // V1
                VQ[m] = sBuf[2][m * NF + lane];   // V0
            }
            float O[9];
            couple1<4, 0>(U0, U1, VP, VQ, wtd, O);
            float wd = kp.wdip[lane];
            float d0 = warp_sum(O[1] * wd);
            float d1 = warp_sum(O[2] * wd);
            float d2 = warp_sum(O[3] * wd);
            if (lane == 0) {
                g_dip[node * 3 + 0] = d0;
                g_dip[node * 3 + 1] = d1;
                g_dip[node * 3 + 2] = d2;
            }
        }
    }
}

// ---------------------------------------------------------------------------
// Fused message pass + node update (+ optional readout).
// One block per node, 128 threads = 4 warps: wid = p*2 + h.
// ---------------------------------------------------------------------------
template<int MD, bool RO>
__global__ void __launch_bounds__(128) msgupd_kernel(int inbuf, int iter, KParams kp) {
    __shared__ float sBuf[4][9 * NF];
    __shared__ float sScr[4][5 * NF];
    __shared__ float sG[NF];

    int node = blockIdx.x;
    int wid = threadIdx.x >> 5;
    int lane = threadIdx.x & 31;
    int p = wid >> 1;
    int h = wid & 1;

    if (h == 0)
        run_warp<MD, RO, 0>(p, lane, node, inbuf, iter, kp, sBuf, sScr[wid], sG);
    else
        run_warp<MD, RO, 1>(p, lane, node, inbuf, iter, kp, sBuf, sScr[wid], sG);
}

// ---------------------------------------------------------------------------
// Per-molecule reduction: energy (+Coulomb), dipole
// ---------------------------------------------------------------------------
__global__ void __launch_bounds__(32) reduce_kernel(
    const float* __restrict__ pos,
    const int* __restrict__ dst_idx, const int* __restrict__ src_idx,
    float* __restrict__ out) {
    int mol = blockIdx.x;
    int lane = threadIdx.x;
    int node = mol * NATOM + lane;

    float px = pos[node * 3 + 0], py = pos[node * 3 + 1], pz = pos[node * 3 + 2];
    float cx = warp_sum(px) * (1.0f / 32.0f);
    float cy = warp_sum(py) * (1.0f / 32.0f);
    float cz = warp_sum(pz) * (1.0f / 32.0f);

    float e = warp_sum(g_aE[node]);
    float q = g_q[node];
    float dx = warp_sum(q * (px - cx) + g_dip[node * 3 + 0]);
    float dy = warp_sum(q * (py - cy) + g_dip[node * 3 + 1]);
    float dz = warp_sum(q * (pz - cz) + g_dip[node * 3 + 2]);

    float cacc = 0.0f;
    for (int t = 0; t < 31; t++) {
        int k = t * 32 + lane;
        int e_idx = mol * EPM + k;
        int s = src_idx[k] + mol * NATOM;
        int d = dst_idx[k] + mol * NATOM;
        cacc += g_q[s] * g_q[d] / (g_r[e_idx] + 1e-10f);
    }
    float coul = warp_sum(cacc) * 0.5f;

    if (lane == 0) {
        out[mol] = e + coul * 14.399645f;
        out[NMOL + mol * 3 + 0] = dx;
        out[NMOL + mol * 3 + 1] = dy;
        out[NMOL + mol * 3 + 2] = dz;
    }
}

// ---------------------------------------------------------------------------
// Launch
// ---------------------------------------------------------------------------
extern "C" void kernel_launch(void* const* d_in, const int* in_sizes, int n_in,
                              void* d_out, int out_size) {
    int sft = (n_in >= 24) ? 1 : 0;

    const int*   Zarr   = (const int*)  d_in[0];
    const float* pos    = (const float*)d_in[1];
    const float* Ef     = (const float*)d_in[2];
    const int*   dsti   = (const int*)  d_in[3];
    const int*   srci   = (const int*)  d_in[4];

    KParams kp;
    kp.Wmp    = (const float*)d_in[6 + sft];
    kp.Wd     = (const float*)d_in[7 + sft];
    kp.bd     = (const float*)d_in[8 + sft];
    kp.Wt     = (const float*)d_in[9 + sft];
    kp.Wtd1   = (const float*)d_in[10 + sft];
    kp.Wtd2   = (const float*)d_in[11 + sft];
    kp.Wtdp   = (const float*)d_in[12 + sft];
    kp.Wh     = (const float*)d_in[13 + sft];
    kp.bh     = (const float*)d_in[14 + sft];
    kp.Wq     = (const float*)d_in[15 + sft];
    kp.Wdip1  = (const float*)d_in[16 + sft];
    kp.Wdip2  = (const float*)d_in[17 + sft];
    kp.Wdipp  = (const float*)d_in[18 + sft];
    kp.wdip   = (const float*)d_in[19 + sft];
    kp.We     = (const float*)d_in[20 + sft];
    kp.be     = (const float*)d_in[21 + sft];
    kp.ebias  = (const float*)d_in[22 + sft];
    kp.Zarr   = Zarr;

    const float* embed = (const float*)d_in[5 + sft];
    float* out = (float*)d_out;

    edgeinit_kernel<<<128, 256>>>(pos, dsti, srci, Zarr, embed, Ef);

    msgupd_kernel<2, false><<<NNODE, 128>>>(0, 0, kp);
    msgupd_kernel<2, false><<<NNODE, 128>>>(1, 1, kp);
    msgupd_kernel<0, true><<<NNODE, 128>>>(0, 2, kp);

    reduce_kernel<<<NMOL, 32>>>(pos, dsti, srci, out);
    (void)in_sizes; (void)out_size;
}

// round 13
// speedup vs baseline: 1.1517x; 1.1517x over previous
#include <cuda_runtime.h>
#include <math.h>

// ---------------------------------------------------------------------------
// Constants fixed by setup_inputs
// ---------------------------------------------------------------------------
#define NF      32
#define XS      576        // 2*9*32 floats per node
#define NNODE   1024
#define NMOL    32
#define NATOM   32
#define EPM     992
#define NEDGE   31744

// ---------------------------------------------------------------------------
// Compile-time Clebsch-Gordan per-entry evaluation (replicates _build_cg).
// ---------------------------------------------------------------------------
namespace cg {

__host__ __device__ constexpr double fact(int n) {
    double r = 1.0; for (int i = 2; i <= n; i++) r *= (double)i; return r;
}

__host__ __device__ constexpr double csqrt(double x) {
    if (x <= 0.0) return 0.0;
    double g = (x > 1.0) ? x : 1.0;
    for (int i = 0; i < 100; i++) g = 0.5 * (g + x / g);
    return g;
}

__host__ __device__ constexpr double cgc(int j1, int m1, int j2, int m2, int J, int M) {
    if (m1 + m2 != M) return 0.0;
    int ad = j1 - j2; if (ad < 0) ad = -ad;
    if (J < ad || J > j1 + j2) return 0.0;
    double pref = (2.0 * J + 1.0) * fact(J + j1 - j2) * fact(J - j1 + j2) * fact(j1 + j2 - J)
                  / fact(j1 + j2 + J + 1);
    pref *= fact(J + M) * fact(J - M) * fact(j1 - m1) * fact(j1 + m1) * fact(j2 - m2) * fact(j2 + m2);
    double s = 0.0;
    for (int k = 0; k <= j1 + j2; k++) {
        int d0 = j1 + j2 - J - k, d1 = j1 - m1 - k, d2 = j2 + m2 - k;
        int d3 = J - j2 + m1 + k, d4 = J - j1 - m2 + k;
        if (d0 < 0 || d1 < 0 || d2 < 0 || d3 < 0 || d4 < 0) continue;
        double t = 1.0 / (fact(k) * fact(d0) * fact(d1) * fact(d2) * fact(d3) * fact(d4));
        s += (k & 1) ? -t : t;
    }
    return csqrt(pref) * s;
}

struct C2 { double re, im; };
struct URow { int n; int col[2]; C2 v[2]; };

__host__ __device__ constexpr URow urow(int l, int rr) {
    URow u{};
    const double R2 = 0.70710678118654752440;
    if (rr == l) { u.n = 1; u.col[0] = l; u.v[0].re = 1.0; u.v[0].im = 0.0; return u; }
    if (rr > l) {
        int m = rr - l; double sg = (m & 1) ? -1.0 : 1.0;
        u.n = 2;
        u.col[0] = l + m; u.v[0].re = sg * R2; u.v[0].im = 0.0;
        u.col[1] = l - m; u.v[1].re = R2;      u.v[1].im = 0.0;
        return u;
    }
    int m = l - rr; double sg = (m & 1) ? -1.0 : 1.0;
    u.n = 2;
    u.col[0] = l - m; u.v[0].re = 0.0; u.v[0].im = R2;
    u.col[1] = l + m; u.v[1].re = 0.0; u.v[1].im = -sg * R2;
    return u;
}

__host__ __device__ constexpr int dm(int i) { return (i == 0) ? 0 : ((i < 4) ? 1 : 2); }

__host__ __device__ constexpr float cg_entry(int A, int B, int C) {
    int l1 = dm(A), l2 = dm(B), l3 = dm(C);
    int a = A - l1 * l1, b = B - l2 * l2, c = C - l3 * l3;
    double gre = 0.0, gim = 0.0;
    int ad = l1 - l2; if (ad < 0) ad = -ad;
    if (l3 >= ad && l3 <= l1 + l2) {
        URow u1 = urow(l1, a), u2 = urow(l2, b), u3 = urow(l3, c);
        for (int i = 0; i < u1.n; i++)
            for (int j = 0; j < u2.n; j++)
                for (int k = 0; k < u3.n; k++) {
                    double cv = cgc(l1, u1.col[i] - l1, l2, u2.col[j] - l2,
                                    l3, u3.col[k] - l3);
                    if (cv == 0.0) continue;
                    double pre = u1.v[i].re * u2.v[j].re - u1.v[i].im * u2.v[j].im;
                    double pim = u1.v[i].re * u2.v[j].im + u1.v[i].im * u2.v[j].re;
                    double re = pre * u3.v[k].re + pim * u3.v[k].im;   // * conj(v3)
                    double im = pim * u3.v[k].re - pre * u3.v[k].im;
                    gre += re * cv; gim += im * cv;
                }
    }
    double agre = (gre < 0) ? -gre : gre;
    double agim = (gim < 0) ? -gim : gim;
    double R = (agim > agre) ? gim : gre;
    return (float)R;
}

__host__ __device__ constexpr bool in_half(int i, int h) { return h == 0 ? (i < 5) : (i >= 5); }

// Is A[a][b] needed for ANY kept output c under maxdeg MD?
__host__ __device__ constexpr bool ab_used(int a, int b, int md) {
    for (int c = 0; c < 9; c++) {
        bool keep = (md == 2) || (c == 0);
        if (keep && cg_entry(a, b, c) != 0.0f) return true;
    }
    return false;
}
__host__ __device__ constexpr bool need_same(int a, int md) {
    for (int b = 0; b < 9; b++)
        if (!(b >= 1 && b <= 3) && ab_used(a, b, md)) return true;
    return false;
}
__host__ __device__ constexpr bool need_flip(int a, int md) {
    for (int b = 1; b <= 3; b++)
        if (ab_used(a, b, md)) return true;
    return false;
}

} // namespace cg

// ---------------------------------------------------------------------------
// Device scratch (static, no allocation)
// ---------------------------------------------------------------------------
__device__ float g_r[NEDGE];
__device__ float g_sh[NEDGE * 12];   // padded to 12 for float4 loads
__device__ float g_rad[NEDGE * 8];

__device__ float g_xbuf[2][NNODE * XS];   // ping-pong node state
__device__ float g_xEF[NNODE * XS];
__device__ float g_q[NNODE];
__device__ float g_aE[NNODE];
__device__ float g_dip[NNODE * 3];

__device__ __forceinline__ float warp_sum(float v) {
#pragma unroll
    for (int o = 16; o; o >>= 1) v += __shfl_xor_sync(0xffffffffu, v, o);
    return v;
}
__device__ __forceinline__ float sigm(float x) { return 1.0f / (1.0f + expf(-x)); }

// ---------------------------------------------------------------------------
// Compile-time helpers (ALL CG queries inside if constexpr — R10 lesson)
// ---------------------------------------------------------------------------
// CG contraction y[c] += CG[a,b,c]*A[ab] (MD-masked outputs only)
template<int AB, int C, int MD>
__device__ __forceinline__ void cg_contract_c(const float (&A)[81], float (&y)[9]) {
    if constexpr (C < 9) {
        constexpr float v = cg::cg_entry(AB / 9, AB % 9, C);
        constexpr bool keep = (MD == 2) || (C == 0);
        if constexpr (v != 0.0f && keep) { y[C] += v * A[AB]; }
        cg_contract_c<AB, C + 1, MD>(A, y);
    }
}
template<int AB, int MD>
__device__ __forceinline__ void cg_contract_ab(const float (&A)[81], float (&y)[9]) {
    if constexpr (AB < 81) {
        cg_contract_c<AB, 0, MD>(A, y);
        cg_contract_ab<AB + 1, MD>(A, y);
    }
}

// per-edge A accumulation (full b range, MD-pruned)
template<int AB, int MD>
__device__ __forceinline__ void accum_ab(float (&A)[81], const float (&xsame)[9],
                                         const float (&xflip)[9], const float (&g)[9]) {
    if constexpr (AB < 81) {
        constexpr int a = AB / 9;
        constexpr int b = AB % 9;
        if constexpr (cg::ab_used(a, b, MD)) {
            float xa = (b >= 1 && b <= 3) ? xflip[a] : xsame[a];
            A[AB] += xa * g[b];
        }
        accum_ab<AB + 1, MD>(A, xsame, xflip, g);
    }
}

// guarded x loads
template<int AA, int MD>
__device__ __forceinline__ void load_x(float (&xsame)[9], float (&xflip)[9],
                                       const float* __restrict__ xs,
                                       int sameoff, int flipoff, int lane) {
    if constexpr (AA < 9) {
        if constexpr (cg::need_same(AA, MD)) xsame[AA] = xs[sameoff + AA * NF + lane];
        else                                 xsame[AA] = 0.0f;
        if constexpr (cg::need_flip(AA, MD)) xflip[AA] = xs[flipoff + AA * NF + lane];
        else                                 xflip[AA] = 0.0f;
        load_x<AA + 1, MD>(xsame, xflip, xs, sameoff, flipoff, lane);
    }
}

// couple producing only outputs c in half H (output parity chosen by VP/VQ)
template<int AB, int C, int MAXC, int H>
__device__ __forceinline__ void couple1_c(const float (&U0)[9], const float (&U1)[9],
                                          const float (&VP)[9], const float (&VQ)[9],
                                          const float (&wt)[27], float (&O)[9]) {
    if constexpr (C < MAXC) {
        constexpr int a = AB / 9;
        constexpr int b = AB % 9;
        constexpr float v = cg::cg_entry(a, b, C);
        if constexpr (v != 0.0f && cg::in_half(C, H)) {
            constexpr int lidx = cg::dm(a) * 9 + cg::dm(b) * 3 + cg::dm(C);
            float wv = v * wt[lidx];
            O[C] += wv * (U0[a] * VP[b] + U1[a] * VQ[b]);
        }
        couple1_c<AB, C + 1, MAXC, H>(U0, U1, VP, VQ, wt, O);
    }
}
template<int AB, int MAXC, int H>
__device__ __forceinline__ void couple1_ab(const float (&U0)[9], const float (&U1)[9],
                                           const float (&VP)[9], const float (&VQ)[9],
                                           const float (&wt)[27], float (&O)[9]) {
    if constexpr (AB < 81) {
        couple1_c<AB, 0, MAXC, H>(U0, U1, VP, VQ, wt, O);
        couple1_ab<AB + 1, MAXC, H>(U0, U1, VP, VQ, wt, O);
    }
}
template<int MAXC, int H>
__device__ __forceinline__ void couple1(const float (&U0)[9], const float (&U1)[9],
                                        const float (&VP)[9], const float (&VQ)[9],
                                        const float (&wt)[27], float (&O)[9]) {
#pragma unroll
    for (int c = 0; c < 9; c++) O[c] = 0.0f;
    couple1_ab<0, MAXC, H>(U0, U1, VP, VQ, wt, O);
}

// ---------------------------------------------------------------------------
// Per-warp dense of NR rows (row-local) via smem staging + float4 LDS.
// ---------------------------------------------------------------------------
template<int NR>
__device__ __forceinline__ void dense_rows(float (&X)[NR], const float* __restrict__ W,
                                           int lane, float* scr) {
    float wc[32];
#pragma unroll
    for (int k = 0; k < 32; k++) wc[k] = W[k * NF + lane];
    __syncwarp();
#pragma unroll
    for (int r = 0; r < NR; r++) scr[r * NF + lane] = X[r];
    __syncwarp();
#pragma unroll
    for (int r = 0; r < NR; r++) {
        const float4* rp = (const float4*)(scr + r * NF);
        float a = 0.0f;
#pragma unroll
        for (int kk = 0; kk < 8; kk++) {
            float4 v = rp[kk];
            a += v.x * wc[kk * 4 + 0] + v.y * wc[kk * 4 + 1]
               + v.z * wc[kk * 4 + 2] + v.w * wc[kk * 4 + 3];
        }
        X[r] = a;
    }
    __syncwarp();
}

// ---------------------------------------------------------------------------
// Fused edge precompute + state init (128 blocks x 256)
// ---------------------------------------------------------------------------
__global__ void __launch_bounds__(256) edgeinit_kernel(
    const float* __restrict__ pos,
    const int* __restrict__ dst_idx, const int* __restrict__ src_idx,
    const int* __restrict__ Zarr, const float* __restrict__ embed,
    const float* __restrict__ Ef) {
    int e = blockIdx.x * 256 + threadIdx.x;
    if (e < NEDGE) {
        int mol = e / EPM, k = e % EPM;
        int d = dst_idx[k] + mol * NATOM;
        int s = src_idx[k] + mol * NATOM;
        float dx = pos[s * 3 + 0] - pos[d * 3 + 0];
        float dy = pos[s * 3 + 1] - pos[d * 3 + 1];
        float dz = pos[s * 3 + 2] - pos[d * 3 + 2];
        float r = sqrtf(dx * dx + dy * dy + dz * dz);
        g_r[e] = r;
        float inv = 1.0f / (r + 1e-10f);
        float x = dx * inv, y = dy * inv, z = dz * inv;
        const float s3 = 1.7320508075688772f;
        g_sh[e * 12 + 0] = 1.0f;
        g_sh[e * 12 + 1] = y;
        g_sh[e * 12 + 2] = z;
        g_sh[e * 12 + 3] = x;
        g_sh[e * 12 + 4] = s3 * x * y;
        g_sh[e * 12 + 5] = s3 * y * z;
        g_sh[e * 12 + 6] = 0.5f * (3.0f * z * z - 1.0f);
        g_sh[e * 12 + 7] = s3 * x * z;
        g_sh[e * 12 + 8] = 0.5f * s3 * (x * x - y * y);

        float fb = 1.0f / (1.0f + r);
        float omf = 1.0f - fb;
        float u2 = (r * 0.2f) * (r * 0.2f);
        float inner = fmaxf(1.0f - u2, 1e-6f);
        float cut = (r < 5.0f) ? expf(1.0f - 1.0f / inner) : 0.0f;
        const float binom[8] = {1.f, 7.f, 21.f, 35.f, 35.f, 21.f, 7.f, 1.f};
        float fp[8], op[8];
        fp[0] = 1.0f; op[0] = 1.0f;
#pragma unroll
        for (int i = 1; i < 8; i++) { fp[i] = fp[i - 1] * fb; op[i] = op[i - 1] * omf; }
#pragma unroll
        for (int i = 0; i < 8; i++)
            g_rad[e * 8 + i] = binom[i] * fp[i] * op[7 - i] * cut;
    }

    int node = blockIdx.x * 8 + (threadIdx.x >> 5);
    int lane = threadIdx.x & 31;
    int mol = node >> 5;
    int Z = Zarr[node];
    float* xo = g_xbuf[0] + node * XS;
    float* xe = g_xEF + node * XS;
    float e0 = Ef[mol * 3 + 0], e1 = Ef[mol * 3 + 1], e2 = Ef[mol * 3 + 2];
#pragma unroll
    for (int p = 0; p < 2; p++)
#pragma unroll
        for (int m = 0; m < 9; m++) {
            float xv = (p == 0 && m == 0) ? embed[Z * NF + lane] : 0.0f;
            float ev = (m == 1) ? e0 : ((m == 2) ? e1 : ((m == 3) ? e2 : 0.0f));
            xo[(p * 9 + m) * NF + lane] = xv;
            xe[(p * 9 + m) * NF + lane] = ev;
        }
}

// ---------------------------------------------------------------------------
// Kernel parameter bundle
// ---------------------------------------------------------------------------
struct KParams {
    const float* Wmp; const float* Wd; const float* bd;
    const float* Wt; const float* Wtd1; const float* Wtd2; const float* Wtdp;
    const float* Wh; const float* bh; const float* Wq;
    const float* Wdip1; const float* Wdip2; const float* Wdipp; const float* wdip;
    const float* We; const float* be; const float* ebias;
    const int* Zarr;
};

// ---------------------------------------------------------------------------
// Per-warp work. Warp (p, H):
//   msg:    parity p, EDGE half H (H=0: t 0..15, H=1: t 16..30), full b range.
//   update: parity p, m-row half H (H=0: rows 0..4, H=1: rows 5..8).
// ---------------------------------------------------------------------------
template<int MD, bool RO, int H>
__device__ __forceinline__ void run_warp(
    int p, int lane, int node, int inbuf, int iter, const KParams& kp,
    float (*sBuf)[9 * NF], float* scr, float* sG) {

    constexpr int NR = (H == 0) ? 5 : 4;
    constexpr int MB = (H == 0) ? 0 : 5;
    constexpr int T0 = (H == 0) ? 0 : 16;
    constexpr int T1 = (H == 0) ? 16 : 31;

    int mol = node >> 5, datom = node & 31;
    const float* xin = g_xbuf[inbuf];

    // ================= message (edge half H, parity p) =================
    float wmp0[8], wmp1[8], wmp2[8];
#pragma unroll
    for (int nb = 0; nb < 8; nb++) {
        wmp0[nb] = kp.Wmp[((iter * 3 + 0) * 8 + nb) * NF + lane];
        wmp1[nb] = kp.Wmp[((iter * 3 + 1) * 8 + nb) * NF + lane];
        wmp2[nb] = kp.Wmp[((iter * 3 + 2) * 8 + nb) * NF + lane];
    }

    float A[81];
#pragma unroll
    for (int i = 0; i < 81; i++) A[i] = 0.0f;

    int ebase = mol * EPM + datom * 31;
    int sameoff = p * 288;
    int flipoff = 288 - sameoff;
    const float* xmol = xin + mol * NATOM * XS;

    for (int t = T0; t < T1; t++) {
        int e = ebase + t;
        int satom = t + (t >= datom ? 1 : 0);
        const float* xs = xmol + satom * XS;

        float4 ra = *(const float4*)(g_rad + e * 8);
        float4 rb = *(const float4*)(g_rad + e * 8 + 4);
        float R0 = ra.x * wmp0[0] + ra.y * wmp0[1] + ra.z * wmp0[2] + ra.w * wmp0[3]
                 + rb.x * wmp0[4] + rb.y * wmp0[5] + rb.z * wmp0[6] + rb.w * wmp0[7];
        float R1 = ra.x * wmp1[0] + ra.y * wmp1[1] + ra.z * wmp1[2] + ra.w * wmp1[3]
                 + rb.x * wmp1[4] + rb.y * wmp1[5] + rb.z * wmp1[6] + rb.w * wmp1[7];
        float R2v = ra.x * wmp2[0] + ra.y * wmp2[1] + ra.z * wmp2[2] + ra.w * wmp2[3]
                  + rb.x * wmp2[4] + rb.y * wmp2[5] + rb.z * wmp2[6] + rb.w * wmp2[7];

        float4 s0 = *(const float4*)(g_sh + e * 12);
        float4 s1 = *(const float4*)(g_sh + e * 12 + 4);
        float  s8 = g_sh[e * 12 + 8];
        float g[9];
        g[0] = s0.x * R0;
        g[1] = s0.y * R1; g[2] = s0.z * R1; g[3] = s0.w * R1;
        g[4] = s1.x * R2v; g[5] = s1.y * R2v; g[6] = s1.z * R2v;
        g[7] = s1.w * R2v; g[8] = s8 * R2v;

        float xsame[9], xflip[9];
        load_x<0, MD>(xsame, xflip, xs, sameoff, flipoff, lane);
        accum_ab<0, MD>(A, xsame, xflip, g);
    }

    float Yp[9];
#pragma unroll
    for (int c = 0; c < 9; c++) Yp[c] = 0.0f;
    cg_contract_ab<0, MD>(A, Yp);

    // stage partial Y; slot = p*2 + H (edge-half partials)
#pragma unroll
    for (int m = 0; m < 9; m++) sBuf[p * 2 + H][m * NF + lane] = Yp[m];
    __syncthreads();

    // total Y for my m-rows
    float Y[NR];
#pragma unroll
    for (int r = 0; r < NR; r++)
        Y[r] = sBuf[p * 2 + 0][(MB + r) * NF + lane] + sBuf[p * 2 + 1][(MB + r) * NF + lane];

    // ================= update (row-split across warps) =================
    float X[NR];
    const float* xg = xin + node * XS + p * 288;
#pragma unroll
    for (int r = 0; r < NR; r++) X[r] = xg[(MB + r) * NF + lane] + Y[r];

    // gate 1 (sigm of parity0 m0 — owned by warp (0,0))
    if (p == 0 && H == 0) sG[lane] = X[0];
    __syncthreads();   // also closes sBuf partial-Y reads
    float gate = sigm(sG[lane]);
#pragma unroll
    for (int r = 0; r < NR; r++) X[r] *= gate;

    // dense Wd (own rows) + bias + gate 2
    dense_rows<NR>(X, kp.Wd + iter * NF * NF, lane, scr);
    if (p == 0 && H == 0) X[0] += kp.bd[iter * NF + lane];
    __syncthreads();
    if (p == 0 && H == 0) sG[lane] = X[0];
    __syncthreads();
    gate = sigm(sG[lane]);
#pragma unroll
    for (int r = 0; r < NR; r++) X[r] *= gate;

    // couple(x, xEF, Wt): stage X -> sBuf[p], E -> sBuf[2+p]
    float* xeg = g_xEF + node * XS + p * 288;
    float E[NR];
#pragma unroll
    for (int r = 0; r < NR; r++) {
        E[r] = xeg[(MB + r) * NF + lane];
        sBuf[p][(MB + r) * NF + lane] = X[r];
        sBuf[2 + p][(MB + r) * NF + lane] = E[r];
    }
    __syncthreads();
    float wt[27];
#pragma unroll
    for (int j = 0; j < 27; j++) wt[j] = kp.Wt[(iter * 27 + j) * NF + lane];
    {
        float U0[9], U1[9], VP[9], VQ[9];
#pragma unroll
        for (int m = 0; m < 9; m++) {
            U0[m] = sBuf[0][m * NF + lane];
            U1[m] = sBuf[1][m * NF + lane];
            VP[m] = sBuf[2 + p][m * NF + lane];
            VQ[m] = sBuf[3 - p][m * NF + lane];
        }
        float O[9];
        couple1<9, H>(U0, U1, VP, VQ, wt, O);
#pragma unroll
        for (int r = 0; r < NR; r++) {
            xeg[(MB + r) * NF + lane] = O[MB + r];
            X[r] += O[MB + r];
        }
    }

    // tensor_dense: U = X@Wtd1, V = X@Wtd2 (own rows), couple
    float U[NR], V[NR];
#pragma unroll
    for (int r = 0; r < NR; r++) { U[r] = X[r]; V[r] = X[r]; }
    dense_rows<NR>(U, kp.Wtd1 + iter * NF * NF, lane, scr);
    dense_rows<NR>(V, kp.Wtd2 + iter * NF * NF, lane, scr);
    __syncthreads();   // all couple reads done before restaging
#pragma unroll
    for (int r = 0; r < NR; r++) {
        sBuf[p][(MB + r) * NF + lane] = U[r];
        sBuf[2 + p][(MB + r) * NF + lane] = V[r];
    }
    __syncthreads();
#pragma unroll
    for (int j = 0; j < 27; j++) wt[j] = kp.Wtdp[(iter * 27 + j) * NF + lane];
    {
        float U0[9], U1[9], VP[9], VQ[9];
#pragma unroll
        for (int m = 0; m < 9; m++) {
            U0[m] = sBuf[0][m * NF + lane];
            U1[m] = sBuf[1][m * NF + lane];
            VP[m] = sBuf[2 + p][m * NF + lane];
            VQ[m] = sBuf[3 - p][m * NF + lane];
        }
        float O[9];
        couple1<9, H>(U0, U1, VP, VQ, wt, O);
#pragma unroll
        for (int r = 0; r < NR; r++) X[r] = O[MB + r] + Y[r];
    }

    if constexpr (!RO) {
        float* xo = g_xbuf[inbuf ^ 1] + node * XS + p * 288;
#pragma unroll
        for (int r = 0; r < NR; r++) xo[(MB + r) * NF + lane] = X[r];
        return;
    } else {
        // ================= readout (row-split) =================
#pragma unroll
        for (int i = 0; i < 4; i++) {
            dense_rows<NR>(X, kp.Wh + i * NF * NF, lane, scr);
            if (p == 0 && H == 0) X[0] += kp.bh[i * NF + lane];
            __syncthreads();
            if (p == 0 && H == 0) sG[lane] = X[0];
            __syncthreads();
            float g2 = sigm(sG[lane]);
#pragma unroll
            for (int r = 0; r < NR; r++) X[r] *= g2;
        }
        dense_rows<NR>(X, kp.Wh + 4 * NF * NF, lane, scr);
        if (p == 0 && H == 0) X[0] += kp.bh[4 * NF + lane];

        // charges + site energy (warp (0,0))
        if (p == 0 && H == 0) {
            float scal = X[0];
            float q = warp_sum(scal * kp.Wq[lane]);
            float ae = warp_sum(scal * kp.We[lane]);
            if (lane == 0) {
                g_q[node] = q;
                g_aE[node] = ae + kp.be[0] + kp.ebias[kp.Zarr[node]];
            }
        }

        // dipole path: xd keeps [p0,m0] and [p1,m1..3] (both in row-half 0)
        float Ud[NR], Vd[NR];
#pragma unroll
        for (int r = 0; r < NR; r++) Ud[r] = 0.0f;
        if constexpr (H == 0) {
            if (p == 0) { Ud[0] = X[0]; }
            else        { Ud[1] = X[1]; Ud[2] = X[2]; Ud[3] = X[3]; }
        }
#pragma unroll
        for (int r = 0; r < NR; r++) Vd[r] = Ud[r];
        dense_rows<NR>(Ud, kp.Wdip1, lane, scr);
        dense_rows<NR>(Vd, kp.Wdip2, lane, scr);
        __syncthreads();
#pragma unroll
        for (int r = 0; r < NR; r++) {
            sBuf[p][(MB + r) * NF + lane] = Ud[r];
            sBuf[2 + p][(MB + r) * NF + lane] = Vd[r];
        }
        __syncthreads();

        // dipole couple: output parity 1, c in 1..3 (half 0) -> warp (1,0)
        if (H == 0 && p == 1) {
            float wtd[27];
#pragma unroll
            for (int j = 0; j < 27; j++) wtd[j] = kp.Wdipp[j * NF + lane];
            float U0[9], U1[9], VP[9], VQ[9];
#pragma unroll
            for (int m = 0; m < 9; m++) {
                U0[m] = sBuf[0][m * NF + lane];
                U1[m] = sBuf[1][m * NF + lane];
                VP[m] = sBuf[3][m * NF + lane];   // V1
                VQ[m] = sBuf[2][m * NF + lane];   // V0
            }
            float O[9];
            couple1<4, 0>(U0, U1, VP, VQ, wtd, O);
            float wd = kp.wdip[lane];
            float d0 = warp_sum(O[1] * wd);
            float d1 = warp_sum(O[2] * wd);
            float d2 = warp_sum(O[3] * wd);
            if (lane == 0) {
                g_dip[node * 3 + 0] = d0;
                g_dip[node * 3 + 1] = d1;
                g_dip[node * 3 + 2] = d2;
            }
        }
    }
}

// ---------------------------------------------------------------------------
// Fused message pass + node update (+ optional readout).
// One block per node, 128 threads = 4 warps: wid = p*2 + h.
// ---------------------------------------------------------------------------
template<int MD, bool RO>
__global__ void __launch_bounds__(128) msgupd_kernel(int inbuf, int iter, KParams kp) {
    __shared__ float sBuf[4][9 * NF];
    __shared__ float sScr[4][5 * NF];
    __shared__ float sG[NF];

    int node = blockIdx.x;
    int wid = threadIdx.x >> 5;
    int lane = threadIdx.x & 31;
    int p = wid >> 1;
    int h = wid & 1;

    if (h == 0)
        run_warp<MD, RO, 0>(p, lane, node, inbuf, iter, kp, sBuf, sScr[wid], sG);
    else
        run_warp<MD, RO, 1>(p, lane, node, inbuf, iter, kp, sBuf, sScr[wid], sG);
}

// ---------------------------------------------------------------------------
// Per-molecule reduction: energy (+Coulomb), dipole
// ---------------------------------------------------------------------------
__global__ void __launch_bounds__(32) reduce_kernel(
    const float* __restrict__ pos,
    const int* __restrict__ dst_idx, const int* __restrict__ src_idx,
    float* __restrict__ out) {
    int mol = blockIdx.x;
    int lane = threadIdx.x;
    int node = mol * NATOM + lane;

    float px = pos[node * 3 + 0], py = pos[node * 3 + 1], pz = pos[node * 3 + 2];
    float cx = warp_sum(px) * (1.0f / 32.0f);
    float cy = warp_sum(py) * (1.0f / 32.0f);
    float cz = warp_sum(pz) * (1.0f / 32.0f);

    float e = warp_sum(g_aE[node]);
    float q = g_q[node];
    float dx = warp_sum(q * (px - cx) + g_dip[node * 3 + 0]);
    float dy = warp_sum(q * (py - cy) + g_dip[node * 3 + 1]);
    float dz = warp_sum(q * (pz - cz) + g_dip[node * 3 + 2]);

    float cacc = 0.0f;
    for (int t = 0; t < 31; t++) {
        int k = t * 32 + lane;
        int e_idx = mol * EPM + k;
        int s = src_idx[k] + mol * NATOM;
        int d = dst_idx[k] + mol * NATOM;
        cacc += g_q[s] * g_q[d] / (g_r[e_idx] + 1e-10f);
    }
    float coul = warp_sum(cacc) * 0.5f;

    if (lane == 0) {
        out[mol] = e + coul * 14.399645f;
        out[NMOL + mol * 3 + 0] = dx;
        out[NMOL + mol * 3 + 1] = dy;
        out[NMOL + mol * 3 + 2] = dz;
    }
}

// ---------------------------------------------------------------------------
// Launch
// ---------------------------------------------------------------------------
extern "C" void kernel_launch(void* const* d_in, const int* in_sizes, int n_in,
                              void* d_out, int out_size) {
    int sft = (n_in >= 24) ? 1 : 0;

    const int*   Zarr   = (const int*)  d_in[0];
    const float* pos    = (const float*)d_in[1];
    const float* Ef     = (const float*)d_in[2];
    const int*   dsti   = (const int*)  d_in[3];
    const int*   srci   = (const int*)  d_in[4];

    KParams kp;
    kp.Wmp    = (const float*)d_in[6 + sft];
    kp.Wd     = (const float*)d_in[7 + sft];
    kp.bd     = (const float*)d_in[8 + sft];
    kp.Wt     = (const float*)d_in[9 + sft];
    kp.Wtd1   = (const float*)d_in[10 + sft];
    kp.Wtd2   = (const float*)d_in[11 + sft];
    kp.Wtdp   = (const float*)d_in[12 + sft];
    kp.Wh     = (const float*)d_in[13 + sft];
    kp.bh     = (const float*)d_in[14 + sft];
    kp.Wq     = (const float*)d_in[15 + sft];
    kp.Wdip1  = (const float*)d_in[16 + sft];
    kp.Wdip2  = (const float*)d_in[17 + sft];
    kp.Wdipp  = (const float*)d_in[18 + sft];
    kp.wdip   = (const float*)d_in[19 + sft];
    kp.We     = (const float*)d_in[20 + sft];
    kp.be     = (const float*)d_in[21 + sft];
    kp.ebias  = (const float*)d_in[22 + sft];
    kp.Zarr   = Zarr;

    const float* embed = (const float*)d_in[5 + sft];
    float* out = (float*)d_out;

    edgeinit_kernel<<<128, 256>>>(pos, dsti, srci, Zarr, embed, Ef);

    msgupd_kernel<2, false><<<NNODE, 128>>>(0, 0, kp);
    msgupd_kernel<2, false><<<NNODE, 128>>>(1, 1, kp);
    msgupd_kernel<0, true><<<NNODE, 128>>>(0, 2, kp);

    reduce_kernel<<<NMOL, 32>>>(pos, dsti, srci, out);
    (void)in_sizes; (void)out_size;
}

// round 14
// speedup vs baseline: 1.3686x; 1.1884x over previous
#include <cuda_runtime.h>
#include <math.h>

// ---------------------------------------------------------------------------
// Constants fixed by setup_inputs
// ---------------------------------------------------------------------------
#define NF      32
#define XS      576        // 2*9*32 floats per node
#define NNODE   1024
#define NMOL    32
#define NATOM   32
#define EPM     992
#define NEDGE   31744

// ---------------------------------------------------------------------------
// Compile-time Clebsch-Gordan per-entry evaluation (replicates _build_cg).
// ---------------------------------------------------------------------------
namespace cg {

__host__ __device__ constexpr double fact(int n) {
    double r = 1.0; for (int i = 2; i <= n; i++) r *= (double)i; return r;
}

__host__ __device__ constexpr double csqrt(double x) {
    if (x <= 0.0) return 0.0;
    double g = (x > 1.0) ? x : 1.0;
    for (int i = 0; i < 100; i++) g = 0.5 * (g + x / g);
    return g;
}

__host__ __device__ constexpr double cgc(int j1, int m1, int j2, int m2, int J, int M) {
    if (m1 + m2 != M) return 0.0;
    int ad = j1 - j2; if (ad < 0) ad = -ad;
    if (J < ad || J > j1 + j2) return 0.0;
    double pref = (2.0 * J + 1.0) * fact(J + j1 - j2) * fact(J - j1 + j2) * fact(j1 + j2 - J)
                  / fact(j1 + j2 + J + 1);
    pref *= fact(J + M) * fact(J - M) * fact(j1 - m1) * fact(j1 + m1) * fact(j2 - m2) * fact(j2 + m2);
    double s = 0.0;
    for (int k = 0; k <= j1 + j2; k++) {
        int d0 = j1 + j2 - J - k, d1 = j1 - m1 - k, d2 = j2 + m2 - k;
        int d3 = J - j2 + m1 + k, d4 = J - j1 - m2 + k;
        if (d0 < 0 || d1 < 0 || d2 < 0 || d3 < 0 || d4 < 0) continue;
        double t = 1.0 / (fact(k) * fact(d0) * fact(d1) * fact(d2) * fact(d3) * fact(d4));
        s += (k & 1) ? -t : t;
    }
    return csqrt(pref) * s;
}

struct C2 { double re, im; };
struct URow { int n; int col[2]; C2 v[2]; };

__host__ __device__ constexpr URow urow(int l, int rr) {
    URow u{};
    const double R2 = 0.70710678118654752440;
    if (rr == l) { u.n = 1; u.col[0] = l; u.v[0].re = 1.0; u.v[0].im = 0.0; return u; }
    if (rr > l) {
        int m = rr - l; double sg = (m & 1) ? -1.0 : 1.0;
        u.n = 2;
        u.col[0] = l + m; u.v[0].re = sg * R2; u.v[0].im = 0.0;
        u.col[1] = l - m; u.v[1].re = R2;      u.v[1].im = 0.0;
        return u;
    }
    int m = l - rr; double sg = (m & 1) ? -1.0 : 1.0;
    u.n = 2;
    u.col[0] = l - m; u.v[0].re = 0.0; u.v[0].im = R2;
    u.col[1] = l + m; u.v[1].re = 0.0; u.v[1].im = -sg * R2;
    return u;
}

__host__ __device__ constexpr int dm(int i) { return (i == 0) ? 0 : ((i < 4) ? 1 : 2); }

__host__ __device__ constexpr float cg_entry(int A, int B, int C) {
    int l1 = dm(A), l2 = dm(B), l3 = dm(C);
    int a = A - l1 * l1, b = B - l2 * l2, c = C - l3 * l3;
    double gre = 0.0, gim = 0.0;
    int ad = l1 - l2; if (ad < 0) ad = -ad;
    if (l3 >= ad && l3 <= l1 + l2) {
        URow u1 = urow(l1, a), u2 = urow(l2, b), u3 = urow(l3, c);
        for (int i = 0; i < u1.n; i++)
            for (int j = 0; j < u2.n; j++)
                for (int k = 0; k < u3.n; k++) {
                    double cv = cgc(l1, u1.col[i] - l1, l2, u2.col[j] - l2,
                                    l3, u3.col[k] - l3);
                    if (cv == 0.0) continue;
                    double pre = u1.v[i].re * u2.v[j].re - u1.v[i].im * u2.v[j].im;
                    double pim = u1.v[i].re * u2.v[j].im + u1.v[i].im * u2.v[j].re;
                    double re = pre * u3.v[k].re + pim * u3.v[k].im;   // * conj(v3)
                    double im = pim * u3.v[k].re - pre * u3.v[k].im;
                    gre += re * cv; gim += im * cv;
                }
    }
    double agre = (gre < 0) ? -gre : gre;
    double agim = (gim < 0) ? -gim : gim;
    double R = (agim > agre) ? gim : gre;
    return (float)R;
}

} // namespace cg

// ---------------------------------------------------------------------------
// Device scratch (static, no allocation)
// ---------------------------------------------------------------------------
__device__ float g_r[NEDGE];
__device__ float g_sh[NEDGE * 12];   // padded to 12 for float4 loads
__device__ float g_rad[NEDGE * 8];

__device__ float g_xbuf[2][NNODE * XS];   // ping-pong node state
__device__ float g_xEF[NNODE * XS];
__device__ float g_q[NNODE];
__device__ float g_aE[NNODE];
__device__ float g_dip[NNODE * 3];

__device__ __forceinline__ float warp_sum(float v) {
#pragma unroll
    for (int o = 16; o; o >>= 1) v += __shfl_xor_sync(0xffffffffu, v, o);
    return v;
}
__device__ __forceinline__ float sigm(float x) { return 1.0f / (1.0f + expf(-x)); }

// ---------------------------------------------------------------------------
// Compile-time CG contraction (message pass): y[c] += CG[a,b,c] * A[a*9+b]
// ---------------------------------------------------------------------------
template<int AB, int C, int MD>
__device__ __forceinline__ void cg_contract_c(const float (&A)[81], float (&y)[9]) {
    if constexpr (C < 9) {
        constexpr float v = cg::cg_entry(AB / 9, AB % 9, C);
        constexpr bool keep = (MD == 2) || (C == 0);
        if constexpr (v != 0.0f && keep) { y[C] += v * A[AB]; }
        cg_contract_c<AB, C + 1, MD>(A, y);
    }
}
template<int AB, int MD>
__device__ __forceinline__ void cg_contract_ab(const float (&A)[81], float (&y)[9]) {
    if constexpr (AB < 81) {
        cg_contract_c<AB, 0, MD>(A, y);
        cg_contract_ab<AB + 1, MD>(A, y);
    }
}

// ---------------------------------------------------------------------------
// Single-output-parity couple: O[c] += CG*Wp*(U0[a]*VP[b] + U1[a]*VQ[b]).
// For out-parity 0: (VP,VQ)=(V0,V1); for out-parity 1: (VP,VQ)=(V1,V0).
// ---------------------------------------------------------------------------
template<int AB, int C, int MAXC>
__device__ __forceinline__ void couple1_c(const float (&U0)[9], const float (&U1)[9],
                                          const float (&VP)[9], const float (&VQ)[9],
                                          const float (&wt)[27], float (&O)[9]) {
    if constexpr (C < MAXC) {
        constexpr int a = AB / 9;
        constexpr int b = AB % 9;
        constexpr float v = cg::cg_entry(a, b, C);
        if constexpr (v != 0.0f) {
            constexpr int lidx = cg::dm(a) * 9 + cg::dm(b) * 3 + cg::dm(C);
            float wv = v * wt[lidx];
            O[C] += wv * (U0[a] * VP[b] + U1[a] * VQ[b]);
        }
        couple1_c<AB, C + 1, MAXC>(U0, U1, VP, VQ, wt, O);
    }
}
template<int AB, int MAXC>
__device__ __forceinline__ void couple1_ab(const float (&U0)[9], const float (&U1)[9],
                                           const float (&VP)[9], const float (&VQ)[9],
                                           const float (&wt)[27], float (&O)[9]) {
    if constexpr (AB < 81) {
        couple1_c<AB, 0, MAXC>(U0, U1, VP, VQ, wt, O);
        couple1_ab<AB + 1, MAXC>(U0, U1, VP, VQ, wt, O);
    }
}
template<int MAXC>
__device__ __forceinline__ void couple1(const float (&U0)[9], const float (&U1)[9],
                                        const float (&VP)[9], const float (&VQ)[9],
                                        const float (&wt)[27], float (&O)[9]) {
#pragma unroll
    for (int c = 0; c < 9; c++) O[c] = 0.0f;
    couple1_ab<0, MAXC>(U0, U1, VP, VQ, wt, O);
}

// ---------------------------------------------------------------------------
// Per-warp dense of 9 rows via smem staging + broadcast float4 LDS.
// scr = 288-float per-warp scratch.
// ---------------------------------------------------------------------------
__device__ __forceinline__ void dense1(float (&X)[9], const float* __restrict__ W,
                                       int lane, float* scr) {
    float wc[32];
#pragma unroll
    for (int k = 0; k < 32; k++) wc[k] = W[k * NF + lane];
    __syncwarp();
#pragma unroll
    for (int m = 0; m < 9; m++) scr[m * NF + lane] = X[m];
    __syncwarp();
#pragma unroll
    for (int m = 0; m < 9; m++) {
        const float4* r = (const float4*)(scr + m * NF);
        float a = 0.0f;
#pragma unroll
        for (int kk = 0; kk < 8; kk++) {
            float4 v = r[kk];
            a += v.x * wc[kk * 4 + 0] + v.y * wc[kk * 4 + 1]
               + v.z * wc[kk * 4 + 2] + v.w * wc[kk * 4 + 3];
        }
        X[m] = a;
    }
    __syncwarp();
}

// ---------------------------------------------------------------------------
// Fused edge precompute + state init (128 blocks x 256)
// ---------------------------------------------------------------------------
__global__ void __launch_bounds__(256) edgeinit_kernel(
    const float* __restrict__ pos,
    const int* __restrict__ dst_idx, const int* __restrict__ src_idx,
    const int* __restrict__ Zarr, const float* __restrict__ embed,
    const float* __restrict__ Ef) {
    int e = blockIdx.x * 256 + threadIdx.x;
    if (e < NEDGE) {
        int mol = e / EPM, k = e % EPM;
        int d = dst_idx[k] + mol * NATOM;
        int s = src_idx[k] + mol * NATOM;
        float dx = pos[s * 3 + 0] - pos[d * 3 + 0];
        float dy = pos[s * 3 + 1] - pos[d * 3 + 1];
        float dz = pos[s * 3 + 2] - pos[d * 3 + 2];
        float r = sqrtf(dx * dx + dy * dy + dz * dz);
        g_r[e] = r;
        float inv = 1.0f / (r + 1e-10f);
        float x = dx * inv, y = dy * inv, z = dz * inv;
        const float s3 = 1.7320508075688772f;
        g_sh[e * 12 + 0] = 1.0f;
        g_sh[e * 12 + 1] = y;
        g_sh[e * 12 + 2] = z;
        g_sh[e * 12 + 3] = x;
        g_sh[e * 12 + 4] = s3 * x * y;
        g_sh[e * 12 + 5] = s3 * y * z;
        g_sh[e * 12 + 6] = 0.5f * (3.0f * z * z - 1.0f);
        g_sh[e * 12 + 7] = s3 * x * z;
        g_sh[e * 12 + 8] = 0.5f * s3 * (x * x - y * y);

        float fb = 1.0f / (1.0f + r);
        float omf = 1.0f - fb;
        float u2 = (r * 0.2f) * (r * 0.2f);
        float inner = fmaxf(1.0f - u2, 1e-6f);
        float cut = (r < 5.0f) ? expf(1.0f - 1.0f / inner) : 0.0f;
        const float binom[8] = {1.f, 7.f, 21.f, 35.f, 35.f, 21.f, 7.f, 1.f};
        float fp[8], op[8];
        fp[0] = 1.0f; op[0] = 1.0f;
#pragma unroll
        for (int i = 1; i < 8; i++) { fp[i] = fp[i - 1] * fb; op[i] = op[i - 1] * omf; }
#pragma unroll
        for (int i = 0; i < 8; i++)
            g_rad[e * 8 + i] = binom[i] * fp[i] * op[7 - i] * cut;
    }

    int node = blockIdx.x * 8 + (threadIdx.x >> 5);
    int lane = threadIdx.x & 31;
    int mol = node >> 5;
    int Z = Zarr[node];
    float* xo = g_xbuf[0] + node * XS;
    float* xe = g_xEF + node * XS;
    float e0 = Ef[mol * 3 + 0], e1 = Ef[mol * 3 + 1], e2 = Ef[mol * 3 + 2];
#pragma unroll
    for (int p = 0; p < 2; p++)
#pragma unroll
        for (int m = 0; m < 9; m++) {
            float xv = (p == 0 && m == 0) ? embed[Z * NF + lane] : 0.0f;
            float ev = (m == 1) ? e0 : ((m == 2) ? e1 : ((m == 3) ? e2 : 0.0f));
            xo[(p * 9 + m) * NF + lane] = xv;
            xe[(p * 9 + m) * NF + lane] = ev;
        }
}

// ---------------------------------------------------------------------------
// Kernel parameter bundle
// ---------------------------------------------------------------------------
struct KParams {
    const float* Wmp; const float* Wd; const float* bd;
    const float* Wt; const float* Wtd1; const float* Wtd2; const float* Wtdp;
    const float* Wh; const float* bh; const float* Wq;
    const float* Wdip1; const float* Wdip2; const float* Wdipp; const float* wdip;
    const float* We; const float* be; const float* ebias;
    const int* Zarr;
};

// ---------------------------------------------------------------------------
// Fused message pass + node update (+ optional readout). One block per node,
// 64 threads; warp w owns parity w through msg AND update.
// __launch_bounds__(64, 7): guarantee >=7 blocks/SM so the 1024-block grid
// stays ONE WAVE (reg cap 146 — safe headroom above the ~84-128 autochoice);
// R9 showed losing the single wave costs more than anything else.
// ---------------------------------------------------------------------------
template<int MD, bool RO>
__global__ void __launch_bounds__(64, 7) msgupd_kernel(int inbuf, int iter, KParams kp) {
    __shared__ float sStage[4][9 * NF];   // cross-parity staging (X0,X1,E0,E1)/(U0,U1,V0,V1)
    __shared__ float sScr[2][9 * NF];     // per-warp dense scratch
    __shared__ float sG[NF];              // gate broadcast

    int node = blockIdx.x;
    int w = threadIdx.x >> 5;
    int lane = threadIdx.x & 31;
    int mol = node >> 5, datom = node & 31;
    const float* xin = g_xbuf[inbuf];
    float* scr = sScr[w];

    // ================= message (warp w -> out-parity w) =================
    float wmp0[8], wmp1[8], wmp2[8];
#pragma unroll
    for (int nb = 0; nb < 8; nb++) {
        wmp0[nb] = kp.Wmp[((iter * 3 + 0) * 8 + nb) * NF + lane];
        wmp1[nb] = kp.Wmp[((iter * 3 + 1) * 8 + nb) * NF + lane];
        wmp2[nb] = kp.Wmp[((iter * 3 + 2) * 8 + nb) * NF + lane];
    }

    float A[81];
#pragma unroll
    for (int i = 0; i < 81; i++) A[i] = 0.0f;

    int ebase = mol * EPM + datom * 31;
    int sameoff = w * 288;
    int flipoff = 288 - sameoff;
    const float* xmol = xin + mol * NATOM * XS;

    // unroll 4: batch independent per-edge load groups across iterations to
    // raise MLP (the msg loop is latency-bound on these scattered loads —
    // R11 showed FMA-count reduction alone is neutral).
#pragma unroll 4
    for (int t = 0; t < 31; t++) {
        int e = ebase + t;
        int satom = t + (t >= datom ? 1 : 0);
        const float* xs = xmol + satom * XS;

        float4 ra = *(const float4*)(g_rad + e * 8);
        float4 rb = *(const float4*)(g_rad + e * 8 + 4);
        float R0 = ra.x * wmp0[0] + ra.y * wmp0[1] + ra.z * wmp0[2] + ra.w * wmp0[3]
                 + rb.x * wmp0[4] + rb.y * wmp0[5] + rb.z * wmp0[6] + rb.w * wmp0[7];
        float R1 = ra.x * wmp1[0] + ra.y * wmp1[1] + ra.z * wmp1[2] + ra.w * wmp1[3]
                 + rb.x * wmp1[4] + rb.y * wmp1[5] + rb.z * wmp1[6] + rb.w * wmp1[7];
        float R2v = ra.x * wmp2[0] + ra.y * wmp2[1] + ra.z * wmp2[2] + ra.w * wmp2[3]
                  + rb.x * wmp2[4] + rb.y * wmp2[5] + rb.z * wmp2[6] + rb.w * wmp2[7];

        float4 s0 = *(const float4*)(g_sh + e * 12);
        float4 s1 = *(const float4*)(g_sh + e * 12 + 4);
        float  s8 = g_sh[e * 12 + 8];
        float g[9];
        g[0] = s0.x * R0;
        g[1] = s0.y * R1; g[2] = s0.z * R1; g[3] = s0.w * R1;
        g[4] = s1.x * R2v; g[5] = s1.y * R2v; g[6] = s1.z * R2v;
        g[7] = s1.w * R2v; g[8] = s8 * R2v;

        float xsame[9], xflip[9];
#pragma unroll
        for (int a = 0; a < 9; a++) {
            xsame[a] = xs[sameoff + a * NF + lane];
            xflip[a] = xs[flipoff + a * NF + lane];
        }
#pragma unroll
        for (int a = 0; a < 9; a++)
#pragma unroll
            for (int b = 0; b < 9; b++) {
                float xa = (b >= 1 && b <= 3) ? xflip[a] : xsame[a];
                A[a * 9 + b] += xa * g[b];
            }
    }

    float Y[9];
#pragma unroll
    for (int c = 0; c < 9; c++) Y[c] = 0.0f;
    cg_contract_ab<0, MD>(A, Y);   // Y = msg for parity w

    // ================= update (parity-split across warps) =================
    float X[9];
    const float* xg = xin + node * XS + w * 288;
#pragma unroll
    for (int m = 0; m < 9; m++) X[m] = xg[m * NF + lane] + Y[m];

    // silu gate 1 (gate = sigm of parity0 m0)
    if (w == 0) sG[lane] = X[0];
    __syncthreads();
    float gate = sigm(sG[lane]);
#pragma unroll
    for (int m = 0; m < 9; m++) X[m] *= gate;

    // dense Wd (own parity) + bias + silu gate 2
    dense1(X, kp.Wd + iter * NF * NF, lane, scr);
    if (w == 0) X[0] += kp.bd[iter * NF + lane];
    __syncthreads();
    if (w == 0) sG[lane] = X[0];
    __syncthreads();
    gate = sigm(sG[lane]);
#pragma unroll
    for (int m = 0; m < 9; m++) X[m] *= gate;

    // couple(x, xEF, Wt): stage X and E, compute own out-parity
    float E[9];
    float* xeg = g_xEF + node * XS + w * 288;
#pragma unroll
    for (int m = 0; m < 9; m++) {
        E[m] = xeg[m * NF + lane];
        sStage[w][m * NF + lane] = X[m];       // X0 / X1
        sStage[2 + w][m * NF + lane] = E[m];   // E0 / E1
    }
    __syncthreads();
    float wt[27];
#pragma unroll
    for (int j = 0; j < 27; j++) wt[j] = kp.Wt[(iter * 27 + j) * NF + lane];
    {
        float XA0[9], XA1[9], EP[9], EQ[9];
#pragma unroll
        for (int m = 0; m < 9; m++) {
            XA0[m] = sStage[0][m * NF + lane];
            XA1[m] = sStage[1][m * NF + lane];
            EP[m]  = sStage[2 + w][m * NF + lane];
            EQ[m]  = sStage[3 - w][m * NF + lane];
        }
        float O[9];
        couple1<9>(XA0, XA1, EP, EQ, wt, O);
#pragma unroll
        for (int m = 0; m < 9; m++) {
            xeg[m * NF + lane] = O[m];
            X[m] += O[m];
        }
    }

    // tensor_dense: U = X@Wtd1, V = X@Wtd2 (own parity), couple
    float U[9], V[9];
#pragma unroll
    for (int m = 0; m < 9; m++) { U[m] = X[m]; V[m] = X[m]; }
    dense1(U, kp.Wtd1 + iter * NF * NF, lane, scr);
    dense1(V, kp.Wtd2 + iter * NF * NF, lane, scr);
    __syncthreads();   // previous stage fully consumed
#pragma unroll
    for (int m = 0; m < 9; m++) {
        sStage[w][m * NF + lane] = U[m];       // U0 / U1
        sStage[2 + w][m * NF + lane] = V[m];   // V0 / V1
    }
    __syncthreads();
#pragma unroll
    for (int j = 0; j < 27; j++) wt[j] = kp.Wtdp[(iter * 27 + j) * NF + lane];
    {
        float U0[9], U1[9], VP[9], VQ[9];
#pragma unroll
        for (int m = 0; m < 9; m++) {
            U0[m] = sStage[0][m * NF + lane];
            U1[m] = sStage[1][m * NF + lane];
            VP[m] = sStage[2 + w][m * NF + lane];
            VQ[m] = sStage[3 - w][m * NF + lane];
        }
        float O[9];
        couple1<9>(U0, U1, VP, VQ, wt, O);
#pragma unroll
        for (int m = 0; m < 9; m++) X[m] = O[m] + Y[m];   // final x of this iter
    }

    if constexpr (!RO) {
        float* xo = g_xbuf[inbuf ^ 1] + node * XS + w * 288;
#pragma unroll
        for (int m = 0; m < 9; m++) xo[m * NF + lane] = X[m];
        return;
    } else {
        // ================= readout (fused, parity-split) =================
#pragma unroll
        for (int i = 0; i < 4; i++) {
            dense1(X, kp.Wh + i * NF * NF, lane, scr);
            if (w == 0) X[0] += kp.bh[i * NF + lane];
            __syncthreads();
            if (w == 0) sG[lane] = X[0];
            __syncthreads();
            float g2 = sigm(sG[lane]);
#pragma unroll
            for (int m = 0; m < 9; m++) X[m] *= g2;
        }
        dense1(X, kp.Wh + 4 * NF * NF, lane, scr);
        if (w == 0) X[0] += kp.bh[4 * NF + lane];

        // dipole path: xd keeps [0,0] (parity0) and [1,1:4] (parity1)
        float Ud[9], Vd[9];
#pragma unroll
        for (int m = 0; m < 9; m++) Ud[m] = 0.0f;
        if (w == 0) { Ud[0] = X[0]; }
        else       { Ud[1] = X[1]; Ud[2] = X[2]; Ud[3] = X[3]; }
#pragma unroll
        for (int m = 0; m < 9; m++) Vd[m] = Ud[m];
        dense1(Ud, kp.Wdip1, lane, scr);
        dense1(Vd, kp.Wdip2, lane, scr);
        __syncthreads();
#pragma unroll
        for (int m = 0; m < 9; m++) {
            sStage[w][m * NF + lane] = Ud[m];
            sStage[2 + w][m * NF + lane] = Vd[m];
        }
        __syncthreads();

        if (w == 0) {
            // charges + site energy from scal = X[0] (parity0 m0)
            float scal = X[0];
            float q = warp_sum(scal * kp.Wq[lane]);
            float ae = warp_sum(scal * kp.We[lane]);
            if (lane == 0) {
                g_q[node] = q;
                g_aE[node] = ae + kp.be[0] + kp.ebias[kp.Zarr[node]];
            }
        } else {
            // dipole: O1[c] for c=1..3
            float wtd[27];
#pragma unroll
            for (int j = 0; j < 27; j++) wtd[j] = kp.Wdipp[j * NF + lane];
            float U0[9], U1[9], VP[9], VQ[9];
#pragma unroll
            for (int m = 0; m < 9; m++) {
                U0[m] = sStage[0][m * NF + lane];
                U1[m] = sStage[1][m * NF + lane];
                VP[m] = sStage[3][m * NF + lane];   // out-parity 1: VP=V1
                VQ[m] = sStage[2][m * NF + lane];   // VQ=V0
            }
            float O[9];
            couple1<4>(U0, U1, VP, VQ, wtd, O);
            float wd = kp.wdip[lane];
            float d0 = warp_sum(O[1] * wd);
            float d1 = warp_sum(O[2] * wd);
            float d2 = warp_sum(O[3] * wd);
            if (lane == 0) {
                g_dip[node * 3 + 0] = d0;
                g_dip[node * 3 + 1] = d1;
                g_dip[node * 3 + 2] = d2;
            }
        }
    }
}

// ---------------------------------------------------------------------------
// Per-molecule reduction: energy (+Coulomb), dipole
// ---------------------------------------------------------------------------
__global__ void __launch_bounds__(32) reduce_kernel(
    const float* __restrict__ pos,
    const int* __restrict__ dst_idx, const int* __restrict__ src_idx,
    float* __restrict__ out) {
    int mol = blockIdx.x;
    int lane = threadIdx.x;
    int node = mol * NATOM + lane;

    float px = pos[node * 3 + 0], py = pos[node * 3 + 1], pz = pos[node * 3 + 2];
    float cx = warp_sum(px) * (1.0f / 32.0f);
    float cy = warp_sum(py) * (1.0f / 32.0f);
    float cz = warp_sum(pz) * (1.0f / 32.0f);

    float e = warp_sum(g_aE[node]);
    float q = g_q[node];
    float dx = warp_sum(q * (px - cx) + g_dip[node * 3 + 0]);
    float dy = warp_sum(q * (py - cy) + g_dip[node * 3 + 1]);
    float dz = warp_sum(q * (pz - cz) + g_dip[node * 3 + 2]);

    float cacc = 0.0f;
    for (int t = 0; t < 31; t++) {
        int k = t * 32 + lane;
        int e_idx = mol * EPM + k;
        int s = src_idx[k] + mol * NATOM;
        int d = dst_idx[k] + mol * NATOM;
        cacc += g_q[s] * g_q[d] / (g_r[e_idx] + 1e-10f);
    }
    float coul = warp_sum(cacc) * 0.5f;

    if (lane == 0) {
        out[mol] = e + coul * 14.399645f;
        out[NMOL + mol * 3 + 0] = dx;
        out[NMOL + mol * 3 + 1] = dy;
        out[NMOL + mol * 3 + 2] = dz;
    }
}

// ---------------------------------------------------------------------------
// Launch
// ---------------------------------------------------------------------------
extern "C" void kernel_launch(void* const* d_in, const int* in_sizes, int n_in,
                              void* d_out, int out_size) {
    int sft = (n_in >= 24) ? 1 : 0;

    const int*   Zarr   = (const int*)  d_in[0];
    const float* pos    = (const float*)d_in[1];
    const float* Ef     = (const float*)d_in[2];
    const int*   dsti   = (const int*)  d_in[3];
    const int*   srci   = (const int*)  d_in[4];

    KParams kp;
    kp.Wmp    = (const float*)d_in[6 + sft];
    kp.Wd     = (const float*)d_in[7 + sft];
    kp.bd     = (const float*)d_in[8 + sft];
    kp.Wt     = (const float*)d_in[9 + sft];
    kp.Wtd1   = (const float*)d_in[10 + sft];
    kp.Wtd2   = (const float*)d_in[11 + sft];
    kp.Wtdp   = (const float*)d_in[12 + sft];
    kp.Wh     = (const float*)d_in[13 + sft];
    kp.bh     = (const float*)d_in[14 + sft];
    kp.Wq     = (const float*)d_in[15 + sft];
    kp.Wdip1  = (const float*)d_in[16 + sft];
    kp.Wdip2  = (const float*)d_in[17 + sft];
    kp.Wdipp  = (const float*)d_in[18 + sft];
    kp.wdip   = (const float*)d_in[19 + sft];
    kp.We     = (const float*)d_in[20 + sft];
    kp.be     = (const float*)d_in[21 + sft];
    kp.ebias  = (const float*)d_in[22 + sft];
    kp.Zarr   = Zarr;

    const float* embed = (const float*)d_in[5 + sft];
    float* out = (float*)d_out;

    edgeinit_kernel<<<128, 256>>>(pos, dsti, srci, Zarr, embed, Ef);

    msgupd_kernel<2, false><<<NNODE, 64>>>(0, 0, kp);
    msgupd_kernel<2, false><<<NNODE, 64>>>(1, 1, kp);
    msgupd_kernel<0, true><<<NNODE, 64>>>(0, 2, kp);

    reduce_kernel<<<NMOL, 32>>>(pos, dsti, srci, out);
    (void)in_sizes; (void)out_size;
}